// round 14
// baseline (speedup 1.0000x reference)
#include <cuda_runtime.h>

// Problem constants
#define BB      256
#define LL      500
#define EE      300
#define ROWS    256      // d-rows computed per block (250 outputs + 3 halo each side)
#define OUTR    250      // output rows per block
#define NTHREADS 128
#define NW      18       // 3 aw3 + cw3 + 5 aw5 + cw5 + 7 aw7 + cw7
#define WSTRIDE 320      // padded W row stride (floats), 5 chunks of 64
#define XSTRIDE 68       // shared x row stride (floats): 68 % 32 == 4 -> conflict-free LDS.128
#define CHUNK   64       // E-chunk width (floats)
#define DSTRIDE 19       // shared d row stride (odd -> conflict-free)

typedef unsigned long long u64;

__device__ __forceinline__ u64 fma2(u64 a, u64 b, u64 c) {
    u64 d;
    asm("fma.rn.f32x2 %0, %1, %2, %3;" : "=l"(d) : "l"(a), "l"(b), "l"(c));
    return d;
}

__device__ __forceinline__ float sumpair(u64 v) {
    float lo = __uint_as_float((unsigned)(v & 0xffffffffull));
    float hi = __uint_as_float((unsigned)(v >> 32));
    return lo + hi;
}

template <int NITER>
__device__ __forceinline__ void compute_chunk(const float* __restrict__ swc,
                                              const float* __restrict__ sxA,
                                              const float* __restrict__ sxB,
                                              u64* accA, u64* accB) {
#pragma unroll
    for (int it = 0; it < NITER; ++it) {
        ulonglong2 xa = *reinterpret_cast<const ulonglong2*>(sxA + it * 4);
        ulonglong2 xb = *reinterpret_cast<const ulonglong2*>(sxB + it * 4);
#pragma unroll
        for (int w = 0; w < NW; ++w) {
            ulonglong2 wv = *reinterpret_cast<const ulonglong2*>(swc + w * WSTRIDE + it * 4);
            accA[w] = fma2(xa.x, wv.x, accA[w]);
            accA[w] = fma2(xa.y, wv.y, accA[w]);
            accB[w] = fma2(xb.x, wv.x, accB[w]);
            accB[w] = fma2(xb.y, wv.y, accB[w]);
        }
    }
}

__global__ void __launch_bounds__(NTHREADS, 2)
local_attn_kernel(const float* __restrict__ x,
                  const float* __restrict__ aw3, const float* __restrict__ ab3,
                  const float* __restrict__ cw3, const float* __restrict__ cb3,
                  const float* __restrict__ aw5, const float* __restrict__ ab5,
                  const float* __restrict__ cw5, const float* __restrict__ cb5,
                  const float* __restrict__ aw7, const float* __restrict__ ab7,
                  const float* __restrict__ cw7, const float* __restrict__ cb7,
                  float* __restrict__ out)
{
    extern __shared__ float smem[];
    float* sw = smem;                      // NW * WSTRIDE floats
    float* sx = smem + NW * WSTRIDE;       // ROWS * XSTRIDE floats
    float* sd = sx;                        // reused after compute: ROWS * DSTRIDE floats

    const int tid  = threadIdx.x;
    const int b    = blockIdx.x >> 1;
    const int half = blockIdx.x & 1;
    const int r0   = half * OUTR - 3;      // first (global-l) d-row of this block
    const float* xb = x + (size_t)b * (LL * EE);

    // ---- stage W into shared, zero-padded to WSTRIDE ----
    {
#pragma unroll
        for (int w = 0; w < NW; ++w) {
            const float* src;
            if      (w < 3)  src = aw3 + w * EE;
            else if (w == 3) src = cw3;
            else if (w < 9)  src = aw5 + (w - 4) * EE;
            else if (w == 9) src = cw5;
            else if (w < 17) src = aw7 + (w - 10) * EE;
            else             src = cw7;
            for (int e = tid; e < WSTRIDE; e += NTHREADS)
                sw[w * WSTRIDE + e] = (e < EE) ? src[e] : 0.0f;
        }
    }

    u64 accA[NW], accB[NW];
#pragma unroll
    for (int w = 0; w < NW; ++w) { accA[w] = 0ull; accB[w] = 0ull; }

    // ---- main loop: 5 E-chunks of 64 (last one uses only 44 valid) ----
    for (int c = 0; c < 5; ++c) {
        const int e0 = c * CHUNK;
        __syncthreads();   // protect sx from previous chunk's readers
        // stage x: ROWS rows x 32 float2, coalesced (one warp = one row-chunk)
        for (int i = tid; i < ROWS * (CHUNK / 2); i += NTHREADS) {
            int r  = i >> 5;
            int e2 = i & 31;
            int gl = r0 + r;
            int ge = e0 + e2 * 2;
            float2 v = make_float2(0.0f, 0.0f);
            if (gl >= 0 && gl < LL && ge < EE)
                v = *reinterpret_cast<const float2*>(xb + (size_t)gl * EE + ge);
            *reinterpret_cast<float2*>(sx + r * XSTRIDE + e2 * 2) = v;
        }
        __syncthreads();

        const float* swc = sw + e0;
        const float* sxA = sx + tid * XSTRIDE;
        const float* sxB = sx + (tid + NTHREADS) * XSTRIDE;
        if (c < 4) compute_chunk<16>(swc, sxA, sxB, accA, accB);   // 64 elems
        else       compute_chunk<11>(swc, sxA, sxB, accA, accB);   // 44 elems (256..299)
    }

    // ---- dump d to shared (reuse sx region) ----
    __syncthreads();
#pragma unroll
    for (int w = 0; w < NW; ++w) {
        sd[tid * DSTRIDE + w]              = sumpair(accA[w]);
        sd[(tid + NTHREADS) * DSTRIDE + w] = sumpair(accB[w]);
    }
    __syncthreads();

    // ---- combine: shifts along L + sigmoid gate + tanh projection ----
    const float b3 = ab3[0], c3 = cb3[0];
    const float b5 = ab5[0], c5 = cb5[0];
    const float b7 = ab7[0], c7 = cb7[0];
    const int BL = BB * LL;

    for (int ol = tid; ol < OUTR; ol += NTHREADS) {
        const int dl = ol + 3;                       // local d-row of global l
        const float* dc = sd + dl * DSTRIDE;

        // k=3, p=1: w 0..2 = aw3 rows, w3 = cw3
        float s3 = dc[-DSTRIDE + 0] + dc[1] + dc[DSTRIDE + 2] + b3;
        float g3 = 1.0f / (1.0f + __expf(-s3));
        float o3 = tanhf(dc[3] * g3 + c3);

        // k=5, p=2: w 4..8 = aw5 rows, w9 = cw5
        float s5 = dc[-2 * DSTRIDE + 4] + dc[-DSTRIDE + 5] + dc[6]
                 + dc[DSTRIDE + 7] + dc[2 * DSTRIDE + 8] + b5;
        float g5 = 1.0f / (1.0f + __expf(-s5));
        float o5 = tanhf(dc[9] * g5 + c5);

        // k=7, p=3: w 10..16 = aw7 rows, w17 = cw7
        float s7 = dc[-3 * DSTRIDE + 10] + dc[-2 * DSTRIDE + 11] + dc[-DSTRIDE + 12]
                 + dc[13] + dc[DSTRIDE + 14] + dc[2 * DSTRIDE + 15]
                 + dc[3 * DSTRIDE + 16] + b7;
        float g7 = 1.0f / (1.0f + __expf(-s7));
        float o7 = tanhf(dc[17] * g7 + c7);

        const int gidx = b * LL + half * OUTR + ol;
        out[gidx]          = o3;
        out[BL + gidx]     = o5;
        out[2 * BL + gidx] = o7;
    }
}

extern "C" void kernel_launch(void* const* d_in, const int* in_sizes, int n_in,
                              void* d_out, int out_size) {
    const float* x   = (const float*)d_in[0];
    const float* aw3 = (const float*)d_in[1];
    const float* ab3 = (const float*)d_in[2];
    const float* cw3 = (const float*)d_in[3];
    const float* cb3 = (const float*)d_in[4];
    const float* aw5 = (const float*)d_in[5];
    const float* ab5 = (const float*)d_in[6];
    const float* cw5 = (const float*)d_in[7];
    const float* cb5 = (const float*)d_in[8];
    const float* aw7 = (const float*)d_in[9];
    const float* ab7 = (const float*)d_in[10];
    const float* cw7 = (const float*)d_in[11];
    const float* cb7 = (const float*)d_in[12];
    float* out = (float*)d_out;

    const int smem_bytes = (NW * WSTRIDE + ROWS * XSTRIDE) * (int)sizeof(float); // 92672
    cudaFuncSetAttribute(local_attn_kernel,
                         cudaFuncAttributeMaxDynamicSharedMemorySize, smem_bytes);

    local_attn_kernel<<<BB * 2, NTHREADS, smem_bytes>>>(
        x, aw3, ab3, cw3, cb3, aw5, ab5, cw5, cb5, aw7, ab7, cw7, cb7, out);
}

// round 15
// speedup vs baseline: 1.8857x; 1.8857x over previous
#include <cuda_runtime.h>

// Problem constants
#define BB      256
#define LL      500
#define EE      300
#define ROWS    256      // d-rows computed per block (250 outputs + 3 halo each side)
#define OUTR    250      // output rows per block
#define NTHREADS 128
#define NW      18       // 3 aw3 + cw3 + 5 aw5 + cw5 + 7 aw7 + cw7
#define WSTRIDE 320      // padded W row stride (floats), 10 chunks of 32
#define XSTRIDE 36       // shared x row stride (floats): phase-of-8 banks disjoint -> conflict-free LDS.128
#define CHUNK   32       // E-chunk width (floats)
#define NCHUNK  10       // 9 full chunks + 12-float tail (zero-padded to 32)
#define DSTRIDE 19       // shared d row stride (odd -> conflict-free)

typedef unsigned long long u64;

__device__ __forceinline__ u64 fma2(u64 a, u64 b, u64 c) {
    u64 d;
    asm("fma.rn.f32x2 %0, %1, %2, %3;" : "=l"(d) : "l"(a), "l"(b), "l"(c));
    return d;
}

__device__ __forceinline__ float sumpair(u64 v) {
    float lo = __uint_as_float((unsigned)(v & 0xffffffffull));
    float hi = __uint_as_float((unsigned)(v >> 32));
    return lo + hi;
}

__device__ __forceinline__ void cp_async16(unsigned saddr, const void* gptr, int srcsize) {
    asm volatile("cp.async.cg.shared.global [%0], [%1], 16, %2;"
                 :: "r"(saddr), "l"(gptr), "r"(srcsize));
}

// Stage one 32-float E-chunk for all ROWS rows into sxbuf via cp.async (zfill OOB).
__device__ __forceinline__ void stage_chunk(const float* __restrict__ xb, int r0, int e0,
                                            float* __restrict__ sxbuf, int tid) {
#pragma unroll
    for (int k = 0; k < (ROWS * (CHUNK / 4)) / NTHREADS; ++k) {   // 16
        int t  = tid + k * NTHREADS;
        int r  = t >> 3;          // row
        int j  = t & 7;           // float4 index within chunk
        int gl = r0 + r;
        int ge = e0 + j * 4;
        bool valid = (gl >= 0) && (gl < LL) && (ge + 4 <= EE);
        const float* g = valid ? (xb + (size_t)gl * EE + ge) : xb;
        unsigned sa = (unsigned)__cvta_generic_to_shared(sxbuf + r * XSTRIDE + j * 4);
        cp_async16(sa, g, valid ? 16 : 0);
    }
}

// Compute 8 iterations (32 E-values) of the 18 dot products for 2 rows.
__device__ __forceinline__ void compute_chunk(const float* __restrict__ swc,
                                              const float* __restrict__ sxA,
                                              const float* __restrict__ sxB,
                                              u64* accA, u64* accB) {
#pragma unroll
    for (int it = 0; it < CHUNK / 4; ++it) {
        ulonglong2 xa = *reinterpret_cast<const ulonglong2*>(sxA + it * 4);
        ulonglong2 xb = *reinterpret_cast<const ulonglong2*>(sxB + it * 4);
#pragma unroll
        for (int w = 0; w < NW; ++w) {
            ulonglong2 wv = *reinterpret_cast<const ulonglong2*>(swc + w * WSTRIDE + it * 4);
            accA[w] = fma2(xa.x, wv.x, accA[w]);
            accA[w] = fma2(xa.y, wv.y, accA[w]);
            accB[w] = fma2(xb.x, wv.x, accB[w]);
            accB[w] = fma2(xb.y, wv.y, accB[w]);
        }
    }
}

__global__ void __launch_bounds__(NTHREADS, 2)
local_attn_kernel(const float* __restrict__ x,
                  const float* __restrict__ aw3, const float* __restrict__ ab3,
                  const float* __restrict__ cw3, const float* __restrict__ cb3,
                  const float* __restrict__ aw5, const float* __restrict__ ab5,
                  const float* __restrict__ cw5, const float* __restrict__ cb5,
                  const float* __restrict__ aw7, const float* __restrict__ ab7,
                  const float* __restrict__ cw7, const float* __restrict__ cb7,
                  float* __restrict__ out)
{
    extern __shared__ float smem[];
    float* sw  = smem;                                   // NW * WSTRIDE
    float* sx0 = smem + NW * WSTRIDE;                    // ROWS * XSTRIDE
    float* sx1 = sx0 + ROWS * XSTRIDE;                   // ROWS * XSTRIDE
    float* sd  = sx0;                                    // reused after compute

    const int tid  = threadIdx.x;
    const int b    = blockIdx.x >> 1;
    const int half = blockIdx.x & 1;
    const int r0   = half * OUTR - 3;
    const float* xb = x + (size_t)b * (LL * EE);

    // ---- stage W into shared, zero-padded to WSTRIDE ----
#pragma unroll
    for (int w = 0; w < NW; ++w) {
        const float* src;
        if      (w < 3)  src = aw3 + w * EE;
        else if (w == 3) src = cw3;
        else if (w < 9)  src = aw5 + (w - 4) * EE;
        else if (w == 9) src = cw5;
        else if (w < 17) src = aw7 + (w - 10) * EE;
        else             src = cw7;
        for (int e = tid; e < WSTRIDE; e += NTHREADS)
            sw[w * WSTRIDE + e] = (e < EE) ? src[e] : 0.0f;
    }

    u64 accA[NW], accB[NW];
#pragma unroll
    for (int w = 0; w < NW; ++w) { accA[w] = 0ull; accB[w] = 0ull; }

    // ---- prologue: prefetch chunks 0 and 1 ----
    stage_chunk(xb, r0, 0, sx0, tid);
    asm volatile("cp.async.commit_group;");
    stage_chunk(xb, r0, CHUNK, sx1, tid);
    asm volatile("cp.async.commit_group;");

    // ---- main pipelined loop ----
    for (int c = 0; c < NCHUNK; ++c) {
        if (c < NCHUNK - 1) asm volatile("cp.async.wait_group 1;");
        else                asm volatile("cp.async.wait_group 0;");
        __syncthreads();

        float* buf = (c & 1) ? sx1 : sx0;
        compute_chunk(sw + c * CHUNK,
                      buf + tid * XSTRIDE,
                      buf + (tid + NTHREADS) * XSTRIDE,
                      accA, accB);
        __syncthreads();   // all reads of buf done before restaging it

        if (c + 2 < NCHUNK) {
            stage_chunk(xb, r0, (c + 2) * CHUNK, buf, tid);
            asm volatile("cp.async.commit_group;");
        }
    }

    // ---- dump d to shared (reuse sx0 region) ----
#pragma unroll
    for (int w = 0; w < NW; ++w) {
        sd[tid * DSTRIDE + w]              = sumpair(accA[w]);
        sd[(tid + NTHREADS) * DSTRIDE + w] = sumpair(accB[w]);
    }
    __syncthreads();

    // ---- combine: shifts along L + sigmoid gate + tanh projection ----
    const float b3 = ab3[0], c3 = cb3[0];
    const float b5 = ab5[0], c5 = cb5[0];
    const float b7 = ab7[0], c7 = cb7[0];
    const int BL = BB * LL;

    for (int ol = tid; ol < OUTR; ol += NTHREADS) {
        const int dl = ol + 3;
        const float* dc = sd + dl * DSTRIDE;

        float s3 = dc[-DSTRIDE + 0] + dc[1] + dc[DSTRIDE + 2] + b3;
        float g3 = 1.0f / (1.0f + __expf(-s3));
        float o3 = tanhf(dc[3] * g3 + c3);

        float s5 = dc[-2 * DSTRIDE + 4] + dc[-DSTRIDE + 5] + dc[6]
                 + dc[DSTRIDE + 7] + dc[2 * DSTRIDE + 8] + b5;
        float g5 = 1.0f / (1.0f + __expf(-s5));
        float o5 = tanhf(dc[9] * g5 + c5);

        float s7 = dc[-3 * DSTRIDE + 10] + dc[-2 * DSTRIDE + 11] + dc[-DSTRIDE + 12]
                 + dc[13] + dc[DSTRIDE + 14] + dc[2 * DSTRIDE + 15]
                 + dc[3 * DSTRIDE + 16] + b7;
        float g7 = 1.0f / (1.0f + __expf(-s7));
        float o7 = tanhf(dc[17] * g7 + c7);

        const int gidx = b * LL + half * OUTR + ol;
        out[gidx]          = o3;
        out[BL + gidx]     = o5;
        out[2 * BL + gidx] = o7;
    }
}

extern "C" void kernel_launch(void* const* d_in, const int* in_sizes, int n_in,
                              void* d_out, int out_size) {
    const float* x   = (const float*)d_in[0];
    const float* aw3 = (const float*)d_in[1];
    const float* ab3 = (const float*)d_in[2];
    const float* cw3 = (const float*)d_in[3];
    const float* cb3 = (const float*)d_in[4];
    const float* aw5 = (const float*)d_in[5];
    const float* ab5 = (const float*)d_in[6];
    const float* cw5 = (const float*)d_in[7];
    const float* cb5 = (const float*)d_in[8];
    const float* aw7 = (const float*)d_in[9];
    const float* ab7 = (const float*)d_in[10];
    const float* cw7 = (const float*)d_in[11];
    const float* cb7 = (const float*)d_in[12];
    float* out = (float*)d_out;

    const int smem_bytes = (NW * WSTRIDE + 2 * ROWS * XSTRIDE) * (int)sizeof(float); // 96768
    cudaFuncSetAttribute(local_attn_kernel,
                         cudaFuncAttributeMaxDynamicSharedMemorySize, smem_bytes);

    local_attn_kernel<<<BB * 2, NTHREADS, smem_bytes>>>(
        x, aw3, ab3, cw3, cb3, aw5, ab5, cw5, cb5, aw7, ab7, cw7, cb7, out);
}